// round 8
// baseline (speedup 1.0000x reference)
#include <cuda_runtime.h>
#include <cuda_bf16.h>
#include <cstdint>

// DNN_84026740179139: embedding-bag mean + 3x[64x64 Linear+ReLU].
// R8: two-kernel split; K2 occupancy fix.
//   K1 gather (unchanged from R7): 8192 warps, warp = 2 rows, f32x2 adds.
//   K2 MLP: 256 thr/block, RPB=32, grid 512 -> 4096 warps (2x R7).
//      Tile 4 rows x 2 dims; W DUPLICATED in shared but at 2-dim width this is
//      exactly 1 LDS.128 per k -> inner k-step: 2 LDS.128 + 4 FFMA2, no movs.

#define BATCH   16384
#define DIMS    64
#define NNZ     50

typedef unsigned long long u64;

__device__ __forceinline__ u64 ffma2(u64 a, u64 b, u64 c) {
    u64 d; asm("fma.rn.f32x2 %0, %1, %2, %3;" : "=l"(d) : "l"(a), "l"(b), "l"(c)); return d;
}
__device__ __forceinline__ u64 add2(u64 a, u64 b) {
    u64 d; asm("add.rn.f32x2 %0, %1, %2;" : "=l"(d) : "l"(a), "l"(b)); return d;
}
__device__ __forceinline__ u64 mul2(u64 a, u64 b) {
    u64 d; asm("mul.rn.f32x2 %0, %1, %2;" : "=l"(d) : "l"(a), "l"(b)); return d;
}
__device__ __forceinline__ u64 pack2(float x, float y) {
    u64 d; asm("mov.b64 %0, {%1, %2};" : "=l"(d) : "f"(x), "f"(y)); return d;
}
__device__ __forceinline__ void unpack2(u64 d, float& x, float& y) {
    asm("mov.b64 {%0, %1}, %2;" : "=f"(x), "=f"(y) : "l"(d));
}

// 4MB scratch for pooled embeddings X[BATCH][DIMS]
__device__ float g_X[BATCH * DIMS];

// ================= K1 : gather + mean (unchanged) =================
#define K1_RPB   16
#define K1_THR   256
#define K1_GRID  (BATCH / K1_RPB)   // 1024

__global__ __launch_bounds__(K1_THR) void gather_kernel(
    const float* __restrict__ emb,
    const int*   __restrict__ fidx)
{
    __shared__ int sIdx[K1_RPB * NNZ];     // 3.2 KB

    const int tid = threadIdx.x;
    if (tid < (K1_RPB * NNZ) / 4)
        ((int4*)sIdx)[tid] = ((const int4*)(fidx + blockIdx.x * K1_RPB * NNZ))[tid];
    __syncthreads();

    const int warp = tid >> 5;
    const int lane = tid & 31;
    const int half = lane >> 4;
    const int c    = lane & 15;
    const int lrow = 2 * warp + half;

    const ulonglong2* emb2 = (const ulonglong2*)emb;
    u64 a01 = 0ull, a23 = 0ull;

    #pragma unroll 1
    for (int i0 = 0; i0 < NNZ; i0 += 10) {
        #pragma unroll
        for (int u = 0; u < 10; u++) {
            const int id = sIdx[lrow * NNZ + i0 + u];
            const ulonglong2 v = __ldg(&emb2[(size_t)id * 16 + c]);
            a01 = add2(a01, v.x);
            a23 = add2(a23, v.y);
        }
    }

    const u64 inv2 = pack2(1.0f / NNZ, 1.0f / NNZ);
    a01 = mul2(a01, inv2);
    a23 = mul2(a23, inv2);

    float f0, f1, f2, f3;
    unpack2(a01, f0, f1);
    unpack2(a23, f2, f3);
    const int grow = blockIdx.x * K1_RPB + lrow;
    *(float4*)(g_X + (size_t)grow * DIMS + 4 * c) = make_float4(f0, f1, f2, f3);
}

// ================= K2 : 3x (Linear + ReLU) =================
#define K2_RPB   32
#define K2_THR   256
#define K2_GRID  (BATCH / K2_RPB)   // 512
#define XTS      36                 // sXt row stride (mult of 4 -> 16B-aligned)

__global__ __launch_bounds__(K2_THR) void mlp_kernel(
    const float* __restrict__ W0, const float* __restrict__ b0,
    const float* __restrict__ W1, const float* __restrict__ b1,
    const float* __restrict__ b2, const float* __restrict__ W2,
    float* __restrict__ out)
{
    __shared__ float sW2[DIMS * DIMS * 2];  // 32 KB : W duplicated, (w,w) pairs
    __shared__ float sXt[DIMS * XTS];       // 9.2 KB : x transposed

    const int tid = threadIdx.x;

    // ---- stage W0 duplicated: src float4 i=(k*16+dg) -> dst 2 float4 ----
    {
        const float4* src = (const float4*)W0;
        float4*       dst = (float4*)sW2;
        #pragma unroll
        for (int s = 0; s < 4; s++) {
            const int i = tid + s * K2_THR;
            const float4 w = src[i];
            dst[2 * i + 0] = make_float4(w.x, w.x, w.y, w.y);
            dst[2 * i + 1] = make_float4(w.z, w.z, w.w, w.w);
        }
    }

    // ---- load X tile (coalesced) + transpose into sXt ----
    {
        const float4* X4 = (const float4*)(g_X + (size_t)blockIdx.x * K2_RPB * DIMS);
        #pragma unroll
        for (int s = 0; s < 2; s++) {
            const int idx = tid + s * K2_THR;       // 0..511
            const int row = idx >> 4;               // 0..31
            const int cg  = idx & 15;               // dims 4cg..4cg+3
            const float4 v = X4[idx];
            sXt[(4 * cg + 0) * XTS + row] = v.x;
            sXt[(4 * cg + 1) * XTS + row] = v.y;
            sXt[(4 * cg + 2) * XTS + row] = v.z;
            sXt[(4 * cg + 3) * XTS + row] = v.w;
        }
    }
    __syncthreads();

    // ---- GEMM: thread tile = 4 rows (2 packed pairs) x 2 dims.
    //      r0 = 4*(tid&7)  (rows 0..31), d0 = 2*(tid>>3)  (dims 0..63) ----
    const int r0 = 4 * (tid & 7);
    const int d0 = 2 * (tid >> 3);

    const float* Wn[3] = {W0, W1, W2};
    const float* bn[3] = {b0, b1, b2};

    u64 y2[2][2];    // y2[p][d] = (y[r0+2p][d0+d], y[r0+2p+1][d0+d])

    #pragma unroll
    for (int l = 0; l < 3; l++) {
        {
            const float2 bias = __ldg((const float2*)(bn[l]) + (d0 >> 1));
            const u64 bx = pack2(bias.x, bias.x);
            const u64 by = pack2(bias.y, bias.y);
            y2[0][0] = bx; y2[0][1] = by;
            y2[1][0] = bx; y2[1][1] = by;
        }

        #pragma unroll 16
        for (int k = 0; k < DIMS; k++) {
            // x rows r0..r0+3 as 2 packed pairs: 1 LDS.128, 8 distinct addrs/warp
            const ulonglong2 xx = *(const ulonglong2*)(sXt + k * XTS + r0);
            // duplicated weights (w[d0],w[d0]),(w[d0+1],w[d0+1]): 1 LDS.128, 4 distinct
            const ulonglong2 ww = *(const ulonglong2*)(sW2 + k * (2 * DIMS) + 2 * d0);
            y2[0][0] = ffma2(xx.x, ww.x, y2[0][0]);
            y2[0][1] = ffma2(xx.x, ww.y, y2[0][1]);
            y2[1][0] = ffma2(xx.y, ww.x, y2[1][0]);
            y2[1][1] = ffma2(xx.y, ww.y, y2[1][1]);
        }

        // ReLU
        #pragma unroll
        for (int p = 0; p < 2; p++)
            #pragma unroll
            for (int d = 0; d < 2; d++) {
                float a, b;
                unpack2(y2[p][d], a, b);
                y2[p][d] = pack2(fmaxf(a, 0.f), fmaxf(b, 0.f));
            }

        if (l < 2) {
            __syncthreads();
            // stage next layer's W duplicated
            {
                const float4* src = (const float4*)Wn[l + 1];
                float4*       dst = (float4*)sW2;
                #pragma unroll
                for (int s = 0; s < 4; s++) {
                    const int i = tid + s * K2_THR;
                    const float4 w = src[i];
                    dst[2 * i + 0] = make_float4(w.x, w.x, w.y, w.y);
                    dst[2 * i + 1] = make_float4(w.z, w.z, w.w, w.w);
                }
            }
            // write y back transposed (aligned 8B stores)
            #pragma unroll
            for (int p = 0; p < 2; p++)
                #pragma unroll
                for (int d = 0; d < 2; d++)
                    *(u64*)(sXt + (d0 + d) * XTS + r0 + 2 * p) = y2[p][d];
            __syncthreads();
        }
    }

    // ---- store out[B,64]: 4 rows x 2 dims (8B stores) ----
    #pragma unroll
    for (int p = 0; p < 2; p++) {
        float a0, a1, b0_, b1_;
        unpack2(y2[p][0], a0, b0_);     // rows r0+2p, r0+2p+1 @ dim d0
        unpack2(y2[p][1], a1, b1_);     //                      @ dim d0+1
        const size_t gr = (size_t)blockIdx.x * K2_RPB + r0 + 2 * p;
        *(float2*)(out + gr       * DIMS + d0) = make_float2(a0, a1);
        *(float2*)(out + (gr + 1) * DIMS + d0) = make_float2(b0_, b1_);
    }
}

extern "C" void kernel_launch(void* const* d_in, const int* in_sizes, int n_in,
                              void* d_out, int out_size)
{
    // Resolve inputs by element count:
    //   emb_table 6400000 f32; feature_indices 819200 i32 (first occurrence);
    //   W* 4096 f32 in order; b* 64 f32 in order.
    const float* emb  = nullptr;
    const int*   fidx = nullptr;
    const float* W[3] = {nullptr, nullptr, nullptr};
    const float* b[3] = {nullptr, nullptr, nullptr};
    int wi = 0, bi = 0;

    for (int i = 0; i < n_in; i++) {
        const int sz = in_sizes[i];
        if (sz == 100000 * 64) {
            emb = (const float*)d_in[i];
        } else if (sz == BATCH * NNZ) {
            if (!fidx) fidx = (const int*)d_in[i];
        } else if (sz == DIMS * DIMS) {
            if (wi < 3) W[wi++] = (const float*)d_in[i];
        } else if (sz == DIMS) {
            if (bi < 3) b[bi++] = (const float*)d_in[i];
        }
    }

    float* out = (float*)d_out;
    gather_kernel<<<K1_GRID, K1_THR>>>(emb, fidx);
    mlp_kernel<<<K2_GRID, K2_THR>>>(W[0], b[0], W[1], b[1], b[2], W[2], out);
}

// round 10
// speedup vs baseline: 1.4651x; 1.4651x over previous
#include <cuda_runtime.h>
#include <cuda_bf16.h>
#include <cstdint>

// DNN_84026740179139: embedding-bag mean + 3x[64x64 Linear+ReLU].
// R10 = R9 with XTS fixed to 68 (multiple of 4 -> 16B-aligned ulonglong2 x-loads).
//   K2 tile (r_p=2, d=8): 3 LDS.128 per warp-k for 1024 MACs; crossbar floor
//   ~10.6us, FFMA2 floor ~7.1us; W scalar in shared, duplicated in registers.
// K1 gather unchanged (R7-proven).

#define BATCH   16384
#define DIMS    64
#define NNZ     50

typedef unsigned long long u64;

__device__ __forceinline__ u64 ffma2(u64 a, u64 b, u64 c) {
    u64 d; asm("fma.rn.f32x2 %0, %1, %2, %3;" : "=l"(d) : "l"(a), "l"(b), "l"(c)); return d;
}
__device__ __forceinline__ u64 add2(u64 a, u64 b) {
    u64 d; asm("add.rn.f32x2 %0, %1, %2;" : "=l"(d) : "l"(a), "l"(b)); return d;
}
__device__ __forceinline__ u64 mul2(u64 a, u64 b) {
    u64 d; asm("mul.rn.f32x2 %0, %1, %2;" : "=l"(d) : "l"(a), "l"(b)); return d;
}
__device__ __forceinline__ u64 pack2(float x, float y) {
    u64 d; asm("mov.b64 %0, {%1, %2};" : "=l"(d) : "f"(x), "f"(y)); return d;
}
__device__ __forceinline__ void unpack2(u64 d, float& x, float& y) {
    asm("mov.b64 {%0, %1}, %2;" : "=f"(x), "=f"(y) : "l"(d));
}

// 4MB scratch for pooled embeddings X[BATCH][DIMS]
__device__ float g_X[BATCH * DIMS];

// ================= K1 : gather + mean (unchanged from R7) =================
#define K1_RPB   16
#define K1_THR   256
#define K1_GRID  (BATCH / K1_RPB)   // 1024

__global__ __launch_bounds__(K1_THR) void gather_kernel(
    const float* __restrict__ emb,
    const int*   __restrict__ fidx)
{
    __shared__ int sIdx[K1_RPB * NNZ];     // 3.2 KB

    const int tid = threadIdx.x;
    if (tid < (K1_RPB * NNZ) / 4)
        ((int4*)sIdx)[tid] = ((const int4*)(fidx + blockIdx.x * K1_RPB * NNZ))[tid];
    __syncthreads();

    const int warp = tid >> 5;
    const int lane = tid & 31;
    const int half = lane >> 4;
    const int c    = lane & 15;
    const int lrow = 2 * warp + half;

    const ulonglong2* emb2 = (const ulonglong2*)emb;
    u64 a01 = 0ull, a23 = 0ull;

    #pragma unroll 1
    for (int i0 = 0; i0 < NNZ; i0 += 10) {
        #pragma unroll
        for (int u = 0; u < 10; u++) {
            const int id = sIdx[lrow * NNZ + i0 + u];
            const ulonglong2 v = __ldg(&emb2[(size_t)id * 16 + c]);
            a01 = add2(a01, v.x);
            a23 = add2(a23, v.y);
        }
    }

    const u64 inv2 = pack2(1.0f / NNZ, 1.0f / NNZ);
    a01 = mul2(a01, inv2);
    a23 = mul2(a23, inv2);

    float f0, f1, f2, f3;
    unpack2(a01, f0, f1);
    unpack2(a23, f2, f3);
    const int grow = blockIdx.x * K1_RPB + lrow;
    *(float4*)(g_X + (size_t)grow * DIMS + 4 * c) = make_float4(f0, f1, f2, f3);
}

// ================= K2 : 3x (Linear + ReLU) =================
#define K2_RPB   64
#define K2_THR   128
#define K2_GRID  (BATCH / K2_RPB)   // 256
#define XTS      68                 // sXt row stride in floats (MULT OF 4: 16B align)

__global__ __launch_bounds__(K2_THR) void mlp_kernel(
    const float* __restrict__ W0, const float* __restrict__ b0,
    const float* __restrict__ W1, const float* __restrict__ b1,
    const float* __restrict__ b2, const float* __restrict__ W2,
    float* __restrict__ out)
{
    __shared__ float sW[DIMS * DIMS];      // 16 KB scalar weights
    __shared__ float sXt[DIMS * XTS];      // 17.4 KB x transposed: sXt[k*XTS + r]

    const int tid = threadIdx.x;

    // ---- stage W0 (8 float4/thread, coalesced) ----
    {
        const float4* src = (const float4*)W0;
        float4*       dst = (float4*)sW;
        #pragma unroll
        for (int s = 0; s < 8; s++)
            dst[tid + s * K2_THR] = src[tid + s * K2_THR];
    }

    // ---- load X tile [64 rows x 64] + transpose into sXt ----
    {
        const float4* X4 = (const float4*)(g_X + (size_t)blockIdx.x * K2_RPB * DIMS);
        #pragma unroll
        for (int s = 0; s < 8; s++) {
            const int idx = tid + s * K2_THR;       // 0..1023
            const int row = idx >> 4;               // 0..63
            const int cg  = idx & 15;               // dims 4cg..4cg+3
            const float4 v = X4[idx];
            sXt[(4 * cg + 0) * XTS + row] = v.x;
            sXt[(4 * cg + 1) * XTS + row] = v.y;
            sXt[(4 * cg + 2) * XTS + row] = v.z;
            sXt[(4 * cg + 3) * XTS + row] = v.w;
        }
    }
    __syncthreads();

    // ---- GEMM: thread tile = 4 rows (2 packed pairs) x 8 dims.
    //      rg = tid&15 -> rows 4rg..4rg+3 ; dg = tid>>4 -> dims 8dg..8dg+7 ----
    const int r0 = 4 * (tid & 15);
    const int d0 = 8 * (tid >> 4);

    const float* Wn[3] = {W0, W1, W2};
    const float* bn[3] = {b0, b1, b2};

    u64 y2[2][8];   // y2[p][dd] = (y[r0+2p][d0+dd], y[r0+2p+1][d0+dd])

    #pragma unroll
    for (int l = 0; l < 3; l++) {
        {
            const float4 ba = __ldg((const float4*)(bn[l]) + (d0 >> 2));
            const float4 bb = __ldg((const float4*)(bn[l]) + (d0 >> 2) + 1);
            y2[0][0] = pack2(ba.x, ba.x); y2[0][1] = pack2(ba.y, ba.y);
            y2[0][2] = pack2(ba.z, ba.z); y2[0][3] = pack2(ba.w, ba.w);
            y2[0][4] = pack2(bb.x, bb.x); y2[0][5] = pack2(bb.y, bb.y);
            y2[0][6] = pack2(bb.z, bb.z); y2[0][7] = pack2(bb.w, bb.w);
            #pragma unroll
            for (int dd = 0; dd < 8; dd++) y2[1][dd] = y2[0][dd];
        }

        #pragma unroll 8
        for (int k = 0; k < DIMS; k++) {
            // 4 rows as 2 packed pairs: 1 LDS.128 (16B-aligned: XTS%4==0, r0%4==0)
            const ulonglong2 xv = *(const ulonglong2*)(sXt + k * XTS + r0);
            // 8 scalar weights: 2 LDS.128
            const float4 wa = *(const float4*)(sW + k * DIMS + d0);
            const float4 wb = *(const float4*)(sW + k * DIMS + d0 + 4);
            // duplicate in registers (ALU pipe)
            u64 w2[8];
            w2[0] = pack2(wa.x, wa.x); w2[1] = pack2(wa.y, wa.y);
            w2[2] = pack2(wa.z, wa.z); w2[3] = pack2(wa.w, wa.w);
            w2[4] = pack2(wb.x, wb.x); w2[5] = pack2(wb.y, wb.y);
            w2[6] = pack2(wb.z, wb.z); w2[7] = pack2(wb.w, wb.w);
            #pragma unroll
            for (int dd = 0; dd < 8; dd++) {
                y2[0][dd] = ffma2(xv.x, w2[dd], y2[0][dd]);
                y2[1][dd] = ffma2(xv.y, w2[dd], y2[1][dd]);
            }
        }

        // ReLU
        #pragma unroll
        for (int p = 0; p < 2; p++)
            #pragma unroll
            for (int dd = 0; dd < 8; dd++) {
                float a, b;
                unpack2(y2[p][dd], a, b);
                y2[p][dd] = pack2(fmaxf(a, 0.f), fmaxf(b, 0.f));
            }

        if (l < 2) {
            __syncthreads();
            // stage next layer's W
            {
                const float4* src = (const float4*)Wn[l + 1];
                float4*       dst = (float4*)sW;
                #pragma unroll
                for (int s = 0; s < 8; s++)
                    dst[tid + s * K2_THR] = src[tid + s * K2_THR];
            }
            // write y back transposed (8B stores; (d0+dd)*XTS + r0 + 2p is even)
            #pragma unroll
            for (int p = 0; p < 2; p++)
                #pragma unroll
                for (int dd = 0; dd < 8; dd++)
                    *(u64*)(sXt + (d0 + dd) * XTS + r0 + 2 * p) = y2[p][dd];
            __syncthreads();
        }
    }

    // ---- store out[B,64]: 4 rows x 8 dims = 8 STG.128 ----
    #pragma unroll
    for (int p = 0; p < 2; p++) {
        float lo[8], hi[8];
        #pragma unroll
        for (int dd = 0; dd < 8; dd++) unpack2(y2[p][dd], lo[dd], hi[dd]);
        const size_t gr = (size_t)blockIdx.x * K2_RPB + r0 + 2 * p;
        *(float4*)(out + gr * DIMS + d0)           = make_float4(lo[0], lo[1], lo[2], lo[3]);
        *(float4*)(out + gr * DIMS + d0 + 4)       = make_float4(lo[4], lo[5], lo[6], lo[7]);
        *(float4*)(out + (gr + 1) * DIMS + d0)     = make_float4(hi[0], hi[1], hi[2], hi[3]);
        *(float4*)(out + (gr + 1) * DIMS + d0 + 4) = make_float4(hi[4], hi[5], hi[6], hi[7]);
    }
}

extern "C" void kernel_launch(void* const* d_in, const int* in_sizes, int n_in,
                              void* d_out, int out_size)
{
    // Resolve inputs by element count:
    //   emb_table 6400000 f32; feature_indices 819200 i32 (first occurrence);
    //   W* 4096 f32 in order; b* 64 f32 in order.
    const float* emb  = nullptr;
    const int*   fidx = nullptr;
    const float* W[3] = {nullptr, nullptr, nullptr};
    const float* b[3] = {nullptr, nullptr, nullptr};
    int wi = 0, bi = 0;

    for (int i = 0; i < n_in; i++) {
        const int sz = in_sizes[i];
        if (sz == 100000 * 64) {
            emb = (const float*)d_in[i];
        } else if (sz == BATCH * NNZ) {
            if (!fidx) fidx = (const int*)d_in[i];
        } else if (sz == DIMS * DIMS) {
            if (wi < 3) W[wi++] = (const float*)d_in[i];
        } else if (sz == DIMS) {
            if (bi < 3) b[bi++] = (const float*)d_in[i];
        }
    }

    float* out = (float*)d_out;
    gather_kernel<<<K1_GRID, K1_THR>>>(emb, fidx);
    mlp_kernel<<<K2_GRID, K2_THR>>>(W[0], b[0], W[1], b[1], b[2], W[2], out);
}